// round 3
// baseline (speedup 1.0000x reference)
#include <cuda_runtime.h>

#define NN 100000
#define EE 3200000
#define DD 256
#define D4 64   // DD/4

// ---- scratch (static device memory; no allocations anywhere) ----
__device__ int    g_deg[NN];
__device__ int    g_off[NN + 1];
__device__ int    g_cur[NN];
__device__ int    g_srcs[EE];
__device__ float4 g_agg4[(size_t)NN * D4];   // 102.4 MB
__device__ float4 g_h4[(size_t)NN * D4];     // 102.4 MB

// ---------------- CSC build ----------------
__global__ void k_zero() {
    int i = blockIdx.x * blockDim.x + threadIdx.x;
    if (i < NN) { g_deg[i] = 0; g_cur[i] = 0; }
}

// edge_index arrives as int32: row 0 = src (ei[0..EE)), row 1 = tgt (ei[EE..2EE))
__global__ void k_deg(const int* __restrict__ ei) {
    int e = blockIdx.x * blockDim.x + threadIdx.x;
    if (e < EE) {
        int t = ei[EE + e];
        if (t >= 0 && t < NN) atomicAdd(&g_deg[t], 1);
    }
}

// single-block exclusive scan over 100001 offsets
__global__ void __launch_bounds__(1024) k_scan() {
    __shared__ int sh[1024];
    int tid = threadIdx.x;
    const int chunk = (NN + 1023) / 1024;   // 98
    int lo = tid * chunk;
    int hi = min(lo + chunk, NN);
    int s = 0;
    for (int i = lo; i < hi; i++) s += g_deg[i];
    sh[tid] = s;
    __syncthreads();
    // Hillis-Steele inclusive scan
    for (int d = 1; d < 1024; d <<= 1) {
        int v = (tid >= d) ? sh[tid - d] : 0;
        __syncthreads();
        sh[tid] += v;
        __syncthreads();
    }
    int run = sh[tid] - s;   // exclusive prefix for this chunk
    for (int i = lo; i < hi; i++) { g_off[i] = run; run += g_deg[i]; }
    if (tid == 0) g_off[NN] = EE;
}

__global__ void k_scatter(const int* __restrict__ ei) {
    int e = blockIdx.x * blockDim.x + threadIdx.x;
    if (e < EE) {
        int t = ei[EE + e];
        int s = ei[e];
        if (t >= 0 && t < NN && s >= 0 && s < NN) {
            int p = atomicAdd(&g_cur[t], 1);
            g_srcs[g_off[t] + p] = s;
        }
    }
}

// ---------------- mean aggregation (CSC gather, no atomics) ----------------
// 256 threads/block = 4 nodes x 64 lanes; each lane owns one float4 of the row.
__global__ void __launch_bounds__(256) k_agg(const float4* __restrict__ x4,
                                             float4* __restrict__ out4) {
    int node = blockIdx.x * 4 + (threadIdx.x >> 6);
    int t = threadIdx.x & 63;
    if (node >= NN) return;
    int beg = g_off[node], end = g_off[node + 1];

    float4 a0 = make_float4(0.f, 0.f, 0.f, 0.f);
    float4 a1 = make_float4(0.f, 0.f, 0.f, 0.f);
    int i = beg;
#pragma unroll 4
    for (; i + 2 <= end; i += 2) {
        int s0 = g_srcs[i], s1 = g_srcs[i + 1];
        float4 v0 = x4[(size_t)s0 * D4 + t];
        float4 v1 = x4[(size_t)s1 * D4 + t];
        a0.x += v0.x; a0.y += v0.y; a0.z += v0.z; a0.w += v0.w;
        a1.x += v1.x; a1.y += v1.y; a1.z += v1.z; a1.w += v1.w;
    }
    if (i < end) {
        float4 v = x4[(size_t)g_srcs[i] * D4 + t];
        a0.x += v.x; a0.y += v.y; a0.z += v.z; a0.w += v.w;
    }
    float inv = 1.0f / fmaxf((float)(end - beg), 1.0f);
    float4 r;
    r.x = (a0.x + a1.x) * inv;
    r.y = (a0.y + a1.y) * inv;
    r.z = (a0.z + a1.z) * inv;
    r.w = (a0.w + a1.w) * inv;
    out4[(size_t)node * D4 + t] = r;
}

// ---------------- fused dual GEMM: O = A@W1 + X@W2 + b (+relu) ----------------
// 64x64 tile, BK=16, 256 threads, 4x4 microtile.
__global__ void __launch_bounds__(256) k_gemm(const float* __restrict__ A,
                                              const float* __restrict__ X,
                                              const float* __restrict__ W1,
                                              const float* __restrict__ W2,
                                              const float* __restrict__ bias,
                                              float* __restrict__ O,
                                              int do_relu) {
    __shared__ float As[16][65];
    __shared__ float Bs[16][64];
    int tid  = threadIdx.x;
    int row0 = blockIdx.x * 64;
    int col0 = blockIdx.y * 64;
    int tx = tid & 15, ty = tid >> 4;
    int m0 = ty * 4, n0 = tx * 4;

    // loader coords
    int lr = tid >> 2;          // A-tile row 0..63
    int lc = (tid & 3) * 4;     // A-tile k-col 0,4,8,12
    int wr = tid >> 4;          // W-tile k-row 0..15
    int wc = (tid & 15) * 4;    // W-tile col 0..60

    float acc[4][4];
#pragma unroll
    for (int i = 0; i < 4; i++)
#pragma unroll
        for (int j = 0; j < 4; j++) acc[i][j] = 0.f;

#pragma unroll 1
    for (int phase = 0; phase < 2; phase++) {
        const float* Ain = phase ? X : A;
        const float* Win = phase ? W2 : W1;
#pragma unroll 1
        for (int kt = 0; kt < DD; kt += 16) {
            int gr = row0 + lr;
            float4 av = make_float4(0.f, 0.f, 0.f, 0.f);
            if (gr < NN)
                av = *(const float4*)&Ain[(size_t)gr * DD + kt + lc];
            As[lc + 0][lr] = av.x;
            As[lc + 1][lr] = av.y;
            As[lc + 2][lr] = av.z;
            As[lc + 3][lr] = av.w;

            float4 wv = *(const float4*)&Win[(size_t)(kt + wr) * DD + col0 + wc];
            *(float4*)&Bs[wr][wc] = wv;
            __syncthreads();

#pragma unroll
            for (int kk = 0; kk < 16; kk++) {
                float a[4];
#pragma unroll
                for (int j = 0; j < 4; j++) a[j] = As[kk][m0 + j];
                float4 bv = *(const float4*)&Bs[kk][n0];
                float b[4] = {bv.x, bv.y, bv.z, bv.w};
#pragma unroll
                for (int im = 0; im < 4; im++)
#pragma unroll
                    for (int in = 0; in < 4; in++)
                        acc[im][in] += a[im] * b[in];
            }
            __syncthreads();
        }
    }

    float4 bv = *(const float4*)&bias[col0 + n0];
    float bb[4] = {bv.x, bv.y, bv.z, bv.w};
#pragma unroll
    for (int im = 0; im < 4; im++) {
        int r = row0 + m0 + im;
        if (r < NN) {
            float4 o;
            float v0 = acc[im][0] + bb[0];
            float v1 = acc[im][1] + bb[1];
            float v2 = acc[im][2] + bb[2];
            float v3 = acc[im][3] + bb[3];
            if (do_relu) {
                v0 = fmaxf(v0, 0.f); v1 = fmaxf(v1, 0.f);
                v2 = fmaxf(v2, 0.f); v3 = fmaxf(v3, 0.f);
            }
            o.x = v0; o.y = v1; o.z = v2; o.w = v3;
            *(float4*)&O[(size_t)r * DD + col0 + n0] = o;
        }
    }
}

extern "C" void kernel_launch(void* const* d_in, const int* in_sizes, int n_in,
                              void* d_out, int out_size) {
    const float* x   = (const float*)d_in[0];
    const int*   ei  = (const int*)d_in[1];     // int32 in harness (int64 downcast)
    const float* Wl1 = (const float*)d_in[2];
    const float* b1  = (const float*)d_in[3];
    const float* Wr1 = (const float*)d_in[4];
    const float* Wl2 = (const float*)d_in[5];
    const float* b2  = (const float*)d_in[6];
    const float* Wr2 = (const float*)d_in[7];
    float*       out = (float*)d_out;

    void *agg_p, *h_p;
    cudaGetSymbolAddress(&agg_p, g_agg4);
    cudaGetSymbolAddress(&h_p, g_h4);
    float4* agg4 = (float4*)agg_p;
    float4* h4   = (float4*)h_p;

    // CSC build
    k_zero<<<(NN + 255) / 256, 256>>>();
    k_deg<<<(EE + 255) / 256, 256>>>(ei);
    k_scan<<<1, 1024>>>();
    k_scatter<<<(EE + 255) / 256, 256>>>(ei);

    dim3 ggrid((NN + 63) / 64, DD / 64);

    // layer 1: agg(x) -> gemm -> relu -> h
    k_agg<<<(NN + 3) / 4, 256>>>((const float4*)x, agg4);
    k_gemm<<<ggrid, 256>>>((const float*)agg4, x, Wl1, Wr1, b1, (float*)h4, 1);

    // layer 2: agg(h) -> gemm -> out
    k_agg<<<(NN + 3) / 4, 256>>>((const float4*)h4, agg4);
    k_gemm<<<ggrid, 256>>>((const float*)agg4, (const float*)h4, Wl2, Wr2, b2, out, 0);
}

// round 5
// speedup vs baseline: 1.6186x; 1.6186x over previous
#include <cuda_runtime.h>
#include <cuda_bf16.h>
#include <cstdint>

#define NN 100000
#define EE 3200000
#define DD 256
#define D4 64

__device__ int    g_deg[NN];
__device__ int    g_off[NN + 1];
__device__ int    g_cur[NN];
__device__ int    g_srcs[EE];
__device__ float4 g_agg4[(size_t)NN * D4];
__device__ float4 g_h4[(size_t)NN * D4];

// ---------------- CSC build ----------------
__global__ void k_zero() {
    int i = blockIdx.x * blockDim.x + threadIdx.x;
    if (i < NN) { g_deg[i] = 0; g_cur[i] = 0; }
}

__global__ void k_deg(const int* __restrict__ ei) {
    int e = blockIdx.x * blockDim.x + threadIdx.x;
    if (e < EE) {
        int t = ei[EE + e];
        if (t >= 0 && t < NN) atomicAdd(&g_deg[t], 1);
    }
}

__global__ void __launch_bounds__(1024) k_scan() {
    __shared__ int sh[1024];
    int tid = threadIdx.x;
    const int chunk = (NN + 1023) / 1024;
    int lo = tid * chunk;
    int hi = min(lo + chunk, NN);
    int s = 0;
    for (int i = lo; i < hi; i++) s += g_deg[i];
    sh[tid] = s;
    __syncthreads();
    for (int d = 1; d < 1024; d <<= 1) {
        int v = (tid >= d) ? sh[tid - d] : 0;
        __syncthreads();
        sh[tid] += v;
        __syncthreads();
    }
    int run = sh[tid] - s;
    for (int i = lo; i < hi; i++) { g_off[i] = run; run += g_deg[i]; }
    if (tid == 0) g_off[NN] = EE;
}

__global__ void k_scatter(const int* __restrict__ ei) {
    int e = blockIdx.x * blockDim.x + threadIdx.x;
    if (e < EE) {
        int t = ei[EE + e];
        int s = ei[e];
        if (t >= 0 && t < NN && s >= 0 && s < NN) {
            int p = atomicAdd(&g_cur[t], 1);
            g_srcs[g_off[t] + p] = s;
        }
    }
}

// ---------------- mean aggregation ----------------
__global__ void __launch_bounds__(256) k_agg(const float4* __restrict__ x4,
                                             float4* __restrict__ out4) {
    int node = blockIdx.x * 4 + (threadIdx.x >> 6);
    int t = threadIdx.x & 63;
    if (node >= NN) return;
    int beg = g_off[node];
    int end = g_off[node + 1];

    float4 a0 = make_float4(0.f, 0.f, 0.f, 0.f);
    float4 a1 = make_float4(0.f, 0.f, 0.f, 0.f);
    int i = beg;
    for (; i + 2 <= end; i += 2) {
        int s0 = g_srcs[i];
        int s1 = g_srcs[i + 1];
        float4 v0 = x4[(size_t)s0 * D4 + t];
        float4 v1 = x4[(size_t)s1 * D4 + t];
        a0.x += v0.x; a0.y += v0.y; a0.z += v0.z; a0.w += v0.w;
        a1.x += v1.x; a1.y += v1.y; a1.z += v1.z; a1.w += v1.w;
    }
    if (i < end) {
        float4 v = x4[(size_t)g_srcs[i] * D4 + t];
        a0.x += v.x; a0.y += v.y; a0.z += v.z; a0.w += v.w;
    }
    float inv = 1.0f / fmaxf((float)(end - beg), 1.0f);
    float4 r;
    r.x = (a0.x + a1.x) * inv;
    r.y = (a0.y + a1.y) * inv;
    r.z = (a0.z + a1.z) * inv;
    r.w = (a0.w + a1.w) * inv;
    out4[(size_t)node * D4 + t] = r;
}

// ---------------- tensor-core fused dual GEMM ----------------
// O = A@W1 + X@W2 + b (+relu). fp32 accuracy via bf16 split:
// P@Q ~= Phi@Qhi + Phi@Qlo + Plo@Qhi.
// Block 128x128, BK=32, 8 warps = 4(m) x 2(n), warp tile 32x64.

#define BM 128
#define BN 128
#define BK 32
#define APAD 40
#define BPAD 136

__device__ __forceinline__ unsigned sptr(const void* p) {
    return (unsigned)__cvta_generic_to_shared(p);
}

__device__ __forceinline__ void ldm_x4(unsigned* r, unsigned addr) {
    asm volatile("ldmatrix.sync.aligned.m8n8.x4.shared.b16 {%0,%1,%2,%3}, [%4];"
                 : "=r"(r[0]), "=r"(r[1]), "=r"(r[2]), "=r"(r[3])
                 : "r"(addr));
}

__device__ __forceinline__ void ldm_x4t(unsigned* r, unsigned addr) {
    asm volatile("ldmatrix.sync.aligned.m8n8.x4.trans.shared.b16 {%0,%1,%2,%3}, [%4];"
                 : "=r"(r[0]), "=r"(r[1]), "=r"(r[2]), "=r"(r[3])
                 : "r"(addr));
}

__device__ __forceinline__ void mma_bf16(float* d, const unsigned* a, const unsigned* b) {
    asm volatile("mma.sync.aligned.m16n8k16.row.col.f32.bf16.bf16.f32 "
                 "{%0,%1,%2,%3}, {%4,%5,%6,%7}, {%8,%9}, {%0,%1,%2,%3};"
                 : "+f"(d[0]), "+f"(d[1]), "+f"(d[2]), "+f"(d[3])
                 : "r"(a[0]), "r"(a[1]), "r"(a[2]), "r"(a[3]),
                   "r"(b[0]), "r"(b[1]));
}

// split fp32 pair -> packed bf16 hi pair + lo pair
__device__ __forceinline__ void split2(float x, float y, unsigned* hi, unsigned* lo) {
    __nv_bfloat16 hx = __float2bfloat16(x);
    __nv_bfloat16 hy = __float2bfloat16(y);
    float lx = x - __bfloat162float(hx);
    float ly = y - __bfloat162float(hy);
    __nv_bfloat162 h2 = __halves2bfloat162(hx, hy);
    __nv_bfloat162 l2 = __halves2bfloat162(__float2bfloat16(lx), __float2bfloat16(ly));
    *hi = *(unsigned*)&h2;
    *lo = *(unsigned*)&l2;
}

__global__ void __launch_bounds__(256) k_gemm_tc(const float* __restrict__ A,
                                                 const float* __restrict__ X,
                                                 const float* __restrict__ W1,
                                                 const float* __restrict__ W2,
                                                 const float* __restrict__ bias,
                                                 float* __restrict__ O,
                                                 int do_relu) {
    __shared__ __nv_bfloat16 Ah[BM][APAD];
    __shared__ __nv_bfloat16 Al[BM][APAD];
    __shared__ __nv_bfloat16 Bh[BK][BPAD];
    __shared__ __nv_bfloat16 Bl[BK][BPAD];

    int tid = threadIdx.x;
    int wid = tid >> 5;
    int lane = tid & 31;
    int warp_m = wid >> 1;
    int warp_n = wid & 1;
    int row0 = blockIdx.x * BM;
    int col0 = blockIdx.y * BN;

    float acc[2][8][4];
    for (int i = 0; i < 2; i++) {
        for (int j = 0; j < 8; j++) {
            for (int q = 0; q < 4; q++) {
                acc[i][j][q] = 0.f;
            }
        }
    }

    int ar = tid >> 1;
    int ac = (tid & 1) * 16;
    int br = tid >> 3;
    int bc = (tid & 7) * 16;

    for (int phase = 0; phase < 2; phase++) {
        const float* Ain = phase ? X : A;
        const float* Win = phase ? W2 : W1;

        for (int kt = 0; kt < DD; kt += BK) {
            // load + split A tile (128 x 32)
            int gr = row0 + ar;
            const float* asrc = Ain + (size_t)gr * DD + kt + ac;
            for (int q = 0; q < 4; q++) {
                float4 v = make_float4(0.f, 0.f, 0.f, 0.f);
                if (gr < NN) v = *(const float4*)(asrc + q * 4);
                unsigned h01, l01, h23, l23;
                split2(v.x, v.y, &h01, &l01);
                split2(v.z, v.w, &h23, &l23);
                int c = ac + q * 4;
                *(unsigned*)&Ah[ar][c]     = h01;
                *(unsigned*)&Ah[ar][c + 2] = h23;
                *(unsigned*)&Al[ar][c]     = l01;
                *(unsigned*)&Al[ar][c + 2] = l23;
            }
            // load + split B tile (32 x 128)
            const float* bsrc = Win + (size_t)(kt + br) * DD + col0 + bc;
            for (int q = 0; q < 4; q++) {
                float4 v = *(const float4*)(bsrc + q * 4);
                unsigned h01, l01, h23, l23;
                split2(v.x, v.y, &h01, &l01);
                split2(v.z, v.w, &h23, &l23);
                int c = bc + q * 4;
                *(unsigned*)&Bh[br][c]     = h01;
                *(unsigned*)&Bh[br][c + 2] = h23;
                *(unsigned*)&Bl[br][c]     = l01;
                *(unsigned*)&Bl[br][c + 2] = l23;
            }
            __syncthreads();

            for (int ks = 0; ks < BK; ks += 16) {
                unsigned ah[2][4];
                unsigned al[2][4];
                for (int i = 0; i < 2; i++) {
                    int r = warp_m * 32 + i * 16 + (lane & 15);
                    int c = ks + ((lane >> 4) << 3);
                    ldm_x4(ah[i], sptr(&Ah[r][c]));
                    ldm_x4(al[i], sptr(&Al[r][c]));
                }
                unsigned bh[8][2];
                unsigned bl[8][2];
                for (int j2 = 0; j2 < 4; j2++) {
                    int r = ks + (lane & 15);
                    int c = warp_n * 64 + j2 * 16 + ((lane >> 4) << 3);
                    unsigned t4[4];
                    ldm_x4t(t4, sptr(&Bh[r][c]));
                    bh[j2 * 2][0]     = t4[0];
                    bh[j2 * 2][1]     = t4[1];
                    bh[j2 * 2 + 1][0] = t4[2];
                    bh[j2 * 2 + 1][1] = t4[3];
                    ldm_x4t(t4, sptr(&Bl[r][c]));
                    bl[j2 * 2][0]     = t4[0];
                    bl[j2 * 2][1]     = t4[1];
                    bl[j2 * 2 + 1][0] = t4[2];
                    bl[j2 * 2 + 1][1] = t4[3];
                }
                for (int i = 0; i < 2; i++) {
                    for (int j = 0; j < 8; j++) {
                        mma_bf16(acc[i][j], ah[i], bh[j]);
                        mma_bf16(acc[i][j], ah[i], bl[j]);
                        mma_bf16(acc[i][j], al[i], bh[j]);
                    }
                }
            }
            __syncthreads();
        }
    }

    // epilogue: bias (+relu), fp32 stores
    for (int j = 0; j < 8; j++) {
        int c = col0 + warp_n * 64 + j * 8 + (lane & 3) * 2;
        float2 bb = *(const float2*)(bias + c);
        for (int i = 0; i < 2; i++) {
            int r = row0 + warp_m * 32 + i * 16 + (lane >> 2);
            float v0 = acc[i][j][0] + bb.x;
            float v1 = acc[i][j][1] + bb.y;
            float v2 = acc[i][j][2] + bb.x;
            float v3 = acc[i][j][3] + bb.y;
            if (do_relu) {
                v0 = fmaxf(v0, 0.f);
                v1 = fmaxf(v1, 0.f);
                v2 = fmaxf(v2, 0.f);
                v3 = fmaxf(v3, 0.f);
            }
            if (r < NN) {
                *(float2*)(O + (size_t)r * DD + c) = make_float2(v0, v1);
            }
            if (r + 8 < NN) {
                *(float2*)(O + (size_t)(r + 8) * DD + c) = make_float2(v2, v3);
            }
        }
    }
}

extern "C" void kernel_launch(void* const* d_in, const int* in_sizes, int n_in,
                              void* d_out, int out_size) {
    const float* x   = (const float*)d_in[0];
    const int*   ei  = (const int*)d_in[1];
    const float* Wl1 = (const float*)d_in[2];
    const float* b1  = (const float*)d_in[3];
    const float* Wr1 = (const float*)d_in[4];
    const float* Wl2 = (const float*)d_in[5];
    const float* b2  = (const float*)d_in[6];
    const float* Wr2 = (const float*)d_in[7];
    float*       out = (float*)d_out;

    void* agg_p = 0;
    void* h_p = 0;
    cudaGetSymbolAddress(&agg_p, g_agg4);
    cudaGetSymbolAddress(&h_p, g_h4);
    float4* agg4 = (float4*)agg_p;
    float4* h4   = (float4*)h_p;

    k_zero<<<(NN + 255) / 256, 256>>>();
    k_deg<<<(EE + 255) / 256, 256>>>(ei);
    k_scan<<<1, 1024>>>();
    k_scatter<<<(EE + 255) / 256, 256>>>(ei);

    dim3 ggrid((NN + BM - 1) / BM, DD / BN);

    k_agg<<<(NN + 3) / 4, 256>>>((const float4*)x, agg4);
    k_gemm_tc<<<ggrid, 256>>>((const float*)agg4, x, Wl1, Wr1, b1, (float*)h4, 1);

    k_agg<<<(NN + 3) / 4, 256>>>(h4, agg4);
    k_gemm_tc<<<ggrid, 256>>>((const float*)agg4, (const float*)h4, Wl2, Wr2, b2, out, 0);
}